// round 3
// baseline (speedup 1.0000x reference)
#include <cuda_runtime.h>
#include <cuda_bf16.h>

#define TPB   256
#define NBLK  128                    // 16384 rows * 2 threads / 256
#define SMEM_BYTES (2048 * 16 * 4)   // packed weights, 131072 B

static __device__ __forceinline__ unsigned long long pack2(float a) {
    unsigned long long r;
    asm("mov.b64 %0, {%1, %1};" : "=l"(r) : "f"(a));
    return r;
}
static __device__ __forceinline__ void unpack2(unsigned long long v, float& a, float& b) {
    asm("mov.b64 {%0, %1}, %2;" : "=f"(a), "=f"(b) : "l"(v));
}
static __device__ __forceinline__ unsigned long long ffma2(unsigned long long a,
                                                           unsigned long long b,
                                                           unsigned long long c) {
    unsigned long long d;
    asm("fma.rn.f32x2 %0, %1, %2, %3;" : "=l"(d) : "l"(a), "l"(b), "l"(c));
    return d;
}
static __device__ __forceinline__ unsigned long long fadd2(unsigned long long a,
                                                           unsigned long long b) {
    unsigned long long d;
    asm("add.rn.f32x2 %0, %1, %2;" : "=l"(d) : "l"(a), "l"(b));
    return d;
}

// One fused kernel. 2 threads per row (even lane = h[0:1024), odd = h[1024:2048)).
// Full packed weight matrix lives in smem, interleaved so the two halves'
// broadcast LDS reads land in disjoint bank groups.
__global__ void __launch_bounds__(TPB, 1) fused_k(
    const float* __restrict__ x,
    const float* __restrict__ Wg, const float* __restrict__ bg,
    const float* __restrict__ Wp, const float* __restrict__ bp,
    const float* __restrict__ Wa, const float* __restrict__ ba,
    float* __restrict__ out)
{
    extern __shared__ float ws[];
    const int tid = threadIdx.x;

    // Stage packed weights: slot = (h&1023)*2 + (h>>10), 16 floats per slot.
    // 4 threads cooperate per h (one float4 quarter each) -> low bank conflict.
    for (int idx = tid; idx < 2048 * 4; idx += TPB) {
        int h = idx >> 2, q = idx & 3;
        int slot = ((h & 1023) << 1) | (h >> 10);
        float4 v;
        if (q == 0)      v = *(const float4*)(Wg + h * 4);
        else if (q == 1) v = *(const float4*)(Wp + h * 4);
        else if (q == 2) { const float* a = Wa + h * 5; v = make_float4(a[0], a[1], a[2], a[3]); }
        else             v = make_float4(Wa[h * 5 + 4], 0.f, 0.f, 0.f);
        *(float4*)(ws + slot * 16 + q * 4) = v;
    }
    __syncthreads();

    const int gt   = blockIdx.x * TPB + tid;
    const int row  = gt >> 1;
    const int half = gt & 1;
    const float4* xr = (const float4*)(x + (size_t)row * 2048 + half * 1024);
    const float*  wb = ws + half * 16;

    unsigned long long acc0 = 0, acc1 = 0, acc2 = 0, acc3 = 0,
                       acc4 = 0, acc5 = 0, acc6 = 0;

#pragma unroll 4
    for (int i = 0; i < 256; i++) {
        float4 xv = xr[i];
        const float* wr = wb + (i << 7);   // 4 h's * 32-float stride
#pragma unroll
        for (int j = 0; j < 4; j++) {
            float xs = (j == 0) ? xv.x : (j == 1) ? xv.y : (j == 2) ? xv.z : xv.w;
            unsigned long long x2 = pack2(xs);
            const float* w = wr + (j << 5);
            ulonglong2 wA = *(const ulonglong2*)(w);        // cols 0..3
            ulonglong2 wB = *(const ulonglong2*)(w + 4);    // cols 4..7
            ulonglong2 wC = *(const ulonglong2*)(w + 8);    // cols 8..11
            unsigned long long wD = *(const unsigned long long*)(w + 12); // 12,13(=0)
            acc0 = ffma2(x2, wA.x, acc0);
            acc1 = ffma2(x2, wA.y, acc1);
            acc2 = ffma2(x2, wB.x, acc2);
            acc3 = ffma2(x2, wB.y, acc3);
            acc4 = ffma2(x2, wC.x, acc4);
            acc5 = ffma2(x2, wC.y, acc5);
            acc6 = ffma2(x2, wD,   acc6);
        }
    }

    // Combine the two halves of the row (bfly gives both lanes the sum).
    acc0 = fadd2(acc0, __shfl_xor_sync(0xffffffffu, acc0, 1));
    acc1 = fadd2(acc1, __shfl_xor_sync(0xffffffffu, acc1, 1));
    acc2 = fadd2(acc2, __shfl_xor_sync(0xffffffffu, acc2, 1));
    acc3 = fadd2(acc3, __shfl_xor_sync(0xffffffffu, acc3, 1));
    acc4 = fadd2(acc4, __shfl_xor_sync(0xffffffffu, acc4, 1));
    acc5 = fadd2(acc5, __shfl_xor_sync(0xffffffffu, acc5, 1));
    acc6 = fadd2(acc6, __shfl_xor_sync(0xffffffffu, acc6, 1));

    if (half == 0) {
        float v[14];
        unpack2(acc0, v[0],  v[1]);
        unpack2(acc1, v[2],  v[3]);
        unpack2(acc2, v[4],  v[5]);
        unpack2(acc3, v[6],  v[7]);
        unpack2(acc4, v[8],  v[9]);
        unpack2(acc5, v[10], v[11]);
        unpack2(acc6, v[12], v[13]);

        const float LOG2E = 1.4426950408889634f;
        float G[4], P[4], A[5];
#pragma unroll
        for (int c = 0; c < 4; c++) G[c] = v[c]     + __ldg(bg + c);
#pragma unroll
        for (int c = 0; c < 4; c++) P[c] = v[4 + c] + __ldg(bp + c);
#pragma unroll
        for (int c = 0; c < 5; c++) A[c] = v[8 + c] + __ldg(ba + c);

        float mg = fmaxf(fmaxf(G[0], G[1]), fmaxf(G[2], G[3]));
        float sg = 0.f;
#pragma unroll
        for (int c = 0; c < 4; c++) { G[c] = exp2f((G[c] - mg) * LOG2E); sg += G[c]; }
        float ig = 1.f / sg;
#pragma unroll
        for (int c = 0; c < 4; c++) G[c] *= ig;

        float mp = fmaxf(fmaxf(P[0], P[1]), fmaxf(P[2], P[3]));
        float sp = 0.f;
#pragma unroll
        for (int c = 0; c < 4; c++) { P[c] = exp2f((P[c] - mp) * LOG2E); sp += P[c]; }
        float ip = 1.f / sp;
#pragma unroll
        for (int c = 0; c < 4; c++) P[c] *= ip;

        float ma = fmaxf(fmaxf(fmaxf(A[0], A[1]), fmaxf(A[2], A[3])), A[4]);
        float sa = 0.f;
#pragma unroll
        for (int c = 0; c < 5; c++) { A[c] = exp2f((A[c] - ma) * LOG2E); sa += A[c]; }
        float ia = 1.f / sa;
#pragma unroll
        for (int c = 0; c < 5; c++) A[c] *= ia;

        float u0 = P[0] * G[0] + P[1] * G[1] + P[2] * G[2] + P[3] * G[3]; // stay
        float u1 = P[0] * G[1] + P[2] * G[3];                             // up
        float u2 = P[1] * G[0] + P[3] * G[2];                             // down

        float j0 = A[0] * (1.f - u0);
        float j1 = A[1] * (1.f - u1);
        float j2 = A[2] * (1.f - u2);
        float j3 = A[3];
        float j4 = A[4];
        float inv = 1.f / (j0 + j1 + j2 + j3 + j4);

        float* o = out + (size_t)row * 5;
        o[0] = j0 * inv; o[1] = j1 * inv; o[2] = j2 * inv;
        o[3] = j3 * inv; o[4] = j4 * inv;
    }
}

extern "C" void kernel_launch(void* const* d_in, const int* in_sizes, int n_in,
                              void* d_out, int out_size) {
    const float* x  = (const float*)d_in[0];
    const float* Wg = (const float*)d_in[1];
    const float* bg = (const float*)d_in[2];
    const float* Wp = (const float*)d_in[3];
    const float* bp = (const float*)d_in[4];
    const float* Wa = (const float*)d_in[5];
    const float* ba = (const float*)d_in[6];
    float* out = (float*)d_out;

    cudaFuncSetAttribute(fused_k, cudaFuncAttributeMaxDynamicSharedMemorySize,
                         SMEM_BYTES);
    fused_k<<<NBLK, TPB, SMEM_BYTES>>>(x, Wg, bg, Wp, bp, Wa, ba, out);
}